// round 9
// baseline (speedup 1.0000x reference)
#include <cuda_runtime.h>
#include <stdint.h>

#define NC    32
#define KC    16
#define DSUB  128
#define INF   4096
#define OF    2048
#define MAXTOK 2048

typedef unsigned long long ull;

__device__ float         g_lut[NC * KC * OF];
__device__ unsigned char g_idx[MAXTOK * NC];

// ---- packed f32x2 helpers --------------------------------------------------
__device__ __forceinline__ ull pk2(float x, float y) {
    ull r; asm("mov.b64 %0, {%1,%2};" : "=l"(r) : "f"(x), "f"(y)); return r;
}
__device__ __forceinline__ void upk2(ull v, float& x, float& y) {
    asm("mov.b64 {%0,%1}, %2;" : "=f"(x), "=f"(y) : "l"(v));
}
__device__ __forceinline__ ull fma2(ull a, ull b, ull c) {
    ull d; asm("fma.rn.f32x2 %0, %1, %2, %3;" : "=l"(d) : "l"(a), "l"(b), "l"(c)); return d;
}
// LDS via 32-bit shared-space address + compile-time immediate offset.
// (R8's generic-pointer version executed cvta + 64-bit math per call — ~768
// junk instructions/thread. This is the fix.)
template<int OFF>
__device__ __forceinline__ void lds2(ull& a, ull& b, unsigned s) {
    asm("ld.shared.v2.u64 {%0,%1}, [%2+%3];"
        : "=l"(a), "=l"(b) : "r"(s), "n"(OFF));
}
__device__ __forceinline__ float4 lds4f(unsigned s) {
    float4 v;
    asm("ld.shared.v4.f32 {%0,%1,%2,%3}, [%4];"
        : "=f"(v.x), "=f"(v.y), "=f"(v.z), "=f"(v.w) : "r"(s));
    return v;
}

// smem layout for idx (floats)
#define XS_STRIDE 132
#define IDX_XS    (128 * XS_STRIDE)
#define IDX_CST   (DSUB * KC)
#define IDX_RED   (128 * 17)
#define IDX_C2P   128
#define IDX_C2S   16
#define IDX_FLOATS (IDX_XS + IDX_CST + IDX_RED + IDX_C2P + IDX_C2S)

// ---------------------------------------------------------------------------
// K2: idx[token][c] = argmin_k ( c2[k] - 2 * <x_sub, cent_k> )
// v5: hot loop on 32-bit shared addresses with immediate offsets; math and
// ordering identical to v4 (same output bits).
// ---------------------------------------------------------------------------
__global__ __launch_bounds__(256, 2) void idx_kernel(const float* __restrict__ x,
                                                     const float* __restrict__ cent)
{
    extern __shared__ float sm[];
    float* xs  = sm;                     // [128][XS_STRIDE]
    float* cst = sm + IDX_XS;            // [DSUB][KC]
    float* red = cst + IDX_CST;          // [128][17]
    float* c2p = red + IDX_RED;          // [16][8]
    float* c2s = c2p + IDX_C2P;          // [16]

    const int c   = blockIdx.y;
    const int tb  = blockIdx.x * 128;
    const int tid = threadIdx.x;

    // stage x tile: two 8-deep batches of independent LDG.128, then the STS.
#pragma unroll
    for (int b = 0; b < 2; b++) {
        float4 buf[8];
#pragma unroll
        for (int j = 0; j < 8; j++) {
            int i   = tid + (b * 8 + j) * 256;
            int row = i >> 5;
            int col = (i & 31) * 4;
            buf[j] = *(const float4*)&x[(size_t)(tb + row) * INF + c * DSUB + col];
        }
#pragma unroll
        for (int j = 0; j < 8; j++) {
            int i   = tid + (b * 8 + j) * 256;
            int row = i >> 5;
            int col = (i & 31) * 4;
            *(float4*)&xs[row * XS_STRIDE + col] = buf[j];
        }
    }
    for (int i = tid; i < KC * DSUB; i += 256) {
        int k = i >> 7, d = i & 127;
        cst[d * KC + k] = cent[(c * KC + k) * DSUB + d];
    }
    __syncthreads();

    if (tid < 128) {
        int k = tid >> 3, part = tid & 7;
        float s = 0.f;
        for (int d = part * 16; d < part * 16 + 16; d++) {
            float cv = cst[d * KC + k];
            s = fmaf(cv, cv, s);
        }
        c2p[k * 8 + part] = s;
    }
    __syncthreads();
    if (tid < 16) {
        float s = 0.f;
        for (int p = 0; p < 8; p++) s += c2p[tid * 8 + p];
        c2s[tid] = s;
    }
    __syncthreads();

    const int token = tid & 127;
    const int half  = tid >> 7;
    const int dbase = half * 64;

    ull acc2[8];
#pragma unroll
    for (int p = 0; p < 8; p++) acc2[p] = 0ull;

    const float* xr = &xs[token * XS_STRIDE];
    unsigned x_s   = (unsigned)__cvta_generic_to_shared(xr) + dbase * 4;
    unsigned cst_s = (unsigned)__cvta_generic_to_shared(cst) + dbase * KC * 4;

#pragma unroll 4
    for (int d0 = 0; d0 < 64; d0 += 4) {
        float4 xq = lds4f(x_s);
        x_s += 16;
        float xv4[4] = {xq.x, xq.y, xq.z, xq.w};
#pragma unroll
        for (int j = 0; j < 4; j++) {
            ull xp = pk2(xv4[j], xv4[j]);
            ull a0, a1, a2, a3;
            lds2<0>(a0, a1, cst_s);     // k0..k3
            lds2<16>(a2, a3, cst_s);    // k4..k7
            acc2[0] = fma2(a0, xp, acc2[0]);
            acc2[1] = fma2(a1, xp, acc2[1]);
            acc2[2] = fma2(a2, xp, acc2[2]);
            acc2[3] = fma2(a3, xp, acc2[3]);
            lds2<32>(a0, a1, cst_s);    // k8..k11
            lds2<48>(a2, a3, cst_s);    // k12..k15
            acc2[4] = fma2(a0, xp, acc2[4]);
            acc2[5] = fma2(a1, xp, acc2[5]);
            acc2[6] = fma2(a2, xp, acc2[6]);
            acc2[7] = fma2(a3, xp, acc2[7]);
            cst_s += 64;
        }
    }

    float acc[KC];
#pragma unroll
    for (int p = 0; p < 8; p++) upk2(acc2[p], acc[p * 2], acc[p * 2 + 1]);

    if (half == 1) {
#pragma unroll
        for (int k = 0; k < KC; k++) red[token * 17 + k] = acc[k];
    }
    __syncthreads();
    if (half == 0) {
        float best = 1e30f, second = 1e30f;
        int bi = 0, si = 0;
#pragma unroll
        for (int k = 0; k < KC; k++) {
            float dot = acc[k] + red[token * 17 + k];
            float v = c2s[k] - 2.f * dot;
            if (v < best)        { second = best; si = bi; best = v; bi = k; }
            else if (v < second) { second = v; si = k; }
        }
        if (second - best < 1e-3f) {
            double vb = 0.0, vs = 0.0;
            for (int d = 0; d < DSUB; d++) {
                double xv = (double)xr[d];
                double cb = (double)cst[d * KC + bi];
                double cs = (double)cst[d * KC + si];
                vb += cb * (cb - 2.0 * xv);
                vs += cs * (cs - 2.0 * xv);
            }
            if (vs < vb || (vs == vb && si < bi)) bi = si;
        }
        g_idx[(size_t)(tb + token) * NC + c] = (unsigned char)bi;
    }
}

// ---------------------------------------------------------------------------
// K1: lut — same structure/ordering as R5 (same bits), but hot loop moved to
// 32-bit shared addressing with immediate offsets (removes per-call cvta).
// ---------------------------------------------------------------------------
__global__ __launch_bounds__(512) void lut_kernel(const float* __restrict__ cent,
                                                  const float* __restrict__ weight)
{
    __shared__ float cst[DSUB * KC];
    __shared__ float red[3][KC][128];

    const int c   = blockIdx.y;
    const int tid = threadIdx.x;
    const int dq  = tid >> 7;
    const int col = tid & 127;

    for (int i = tid; i < KC * DSUB; i += 512) {
        int k = i >> 7, d = i & 127;
        cst[d * KC + k] = cent[(c * KC + k) * DSUB + d];
    }
    __syncthreads();

    const int o = blockIdx.x * 128 + col;
    const float* wp = weight + (size_t)c * DSUB * OF + o + (size_t)(dq * 32) * OF;

    ull acc[8];
#pragma unroll
    for (int p = 0; p < 8; p++) acc[p] = 0ull;

    unsigned cst_s = (unsigned)__cvta_generic_to_shared(cst) + (dq * 32) * KC * 4;

#pragma unroll
    for (int half = 0; half < 2; half++) {
        float w[16];
#pragma unroll
        for (int i = 0; i < 16; i++) w[i] = wp[(size_t)(half * 16 + i) * OF];
#pragma unroll
        for (int i = 0; i < 16; i++) {
            ull wv = pk2(w[i], w[i]);
            ull a0, a1, a2, a3;
            // same load order as R5: offsets 0, +8 floats(32B), +4(16B), +12(48B)
            lds2<0>(a0, a1, cst_s);
            lds2<32>(a2, a3, cst_s);
            acc[0] = fma2(a0, wv, acc[0]);
            acc[1] = fma2(a1, wv, acc[1]);
            acc[2] = fma2(a2, wv, acc[2]);
            acc[3] = fma2(a3, wv, acc[3]);
            lds2<16>(a0, a1, cst_s);
            acc[4] = fma2(a0, wv, acc[4]);
            acc[5] = fma2(a1, wv, acc[5]);
            lds2<48>(a2, a3, cst_s);
            acc[6] = fma2(a2, wv, acc[6]);
            acc[7] = fma2(a3, wv, acc[7]);
            cst_s += 64;
        }
    }

    const int kmap[8] = {0, 1, 4, 5, 2, 3, 6, 7};

    if (dq != 0) {
#pragma unroll
        for (int p = 0; p < 8; p++) {
            float v0, v1; upk2(acc[p], v0, v1);
            int kp = kmap[p];
            red[dq - 1][kp * 2 + 0][col] = v0;
            red[dq - 1][kp * 2 + 1][col] = v1;
        }
    }
    __syncthreads();
    if (dq == 0) {
#pragma unroll
        for (int p = 0; p < 8; p++) {
            float v0, v1; upk2(acc[p], v0, v1);
            int k0 = kmap[p] * 2, k1 = k0 + 1;
            v0 = v0 + red[0][k0][col] + red[1][k0][col] + red[2][k0][col];
            v1 = v1 + red[0][k1][col] + red[1][k1][col] + red[2][k1][col];
            g_lut[(size_t)(c * KC + k0) * OF + o] = v0;
            g_lut[(size_t)(c * KC + k1) * OF + o] = v1;
        }
    }
}

// ---------------------------------------------------------------------------
// K3: gather — EXACT Round-4 version (unchanged).
// ---------------------------------------------------------------------------
__global__ __launch_bounds__(256) void gather_kernel(float* __restrict__ out,
                                                     const float* __restrict__ bias)
{
    extern __shared__ float sm[];
    float*         lut_s = sm;
    unsigned char* idx_s = (unsigned char*)(sm + NC * KC * 32);

    const int ob  = blockIdx.x * 32;
    const int tb  = blockIdx.y * 256;
    const int tid = threadIdx.x;

    for (int i = tid; i < NC * KC * 32 / 4; i += 256) {
        int row = i >> 3;
        int col = (i & 7) * 4;
        float4 v = *(const float4*)&g_lut[(size_t)row * OF + ob + col];
        *(float4*)&lut_s[row * 32 + col] = v;
    }
    {
        const uint4* src = (const uint4*)&g_idx[(size_t)tb * NC];
        uint4* dst = (uint4*)idx_s;
        for (int i = tid; i < (256 * NC) / 16; i += 256) dst[i] = src[i];
    }
    __syncthreads();

    const int oi = tid & 31;
    const int tg = tid >> 5;
    const float bv = bias[ob + oi];

    for (int t = tg; t < 256; t += 8) {
        uint4 a = *(const uint4*)&idx_s[t * NC];
        uint4 b = *(const uint4*)&idx_s[t * NC + 16];
        unsigned int iw[8] = {a.x, a.y, a.z, a.w, b.x, b.y, b.z, b.w};
        float s0 = 0.f, s1 = 0.f;
#pragma unroll
        for (int c = 0; c < NC; c++) {
            unsigned int k = (iw[c >> 2] >> ((c & 3) * 8)) & 0xFFu;
            float v = lut_s[(c * KC + k) * 32 + oi];
            if (c & 1) s1 += v;
            else       s0 += v;
        }
        out[(size_t)(tb + t) * OF + ob + oi] = s0 + s1 + bv;
    }
}

// ---------------------------------------------------------------------------
extern "C" void kernel_launch(void* const* d_in, const int* in_sizes, int n_in,
                              void* d_out, int out_size)
{
    const float* x      = (const float*)d_in[0];
    const float* cent   = (const float*)d_in[1];
    const float* weight = (const float*)d_in[2];
    const float* bias   = (const float*)d_in[4];
    float* out = (float*)d_out;

    const int ntok = in_sizes[0] / INF;

    const int IDX_SMEM = IDX_FLOATS * (int)sizeof(float);
    const int G_SMEM   = NC * KC * 32 * (int)sizeof(float) + 256 * NC;

    cudaFuncSetAttribute(idx_kernel,    cudaFuncAttributeMaxDynamicSharedMemorySize, IDX_SMEM);
    cudaFuncSetAttribute(gather_kernel, cudaFuncAttributeMaxDynamicSharedMemorySize, G_SMEM);

    idx_kernel<<<dim3(ntok / 128, NC), 256, IDX_SMEM>>>(x, cent);
    lut_kernel<<<dim3(OF / 128, NC), 512>>>(cent, weight);
    gather_kernel<<<dim3(OF / 32, ntok / 256), 256, G_SMEM>>>(out, bias);
}

// round 10
// speedup vs baseline: 1.5904x; 1.5904x over previous
#include <cuda_runtime.h>
#include <stdint.h>

#define NC    32
#define KC    16
#define DSUB  128
#define INF   4096
#define OF    2048
#define MAXTOK 2048

typedef unsigned long long ull;

__device__ float         g_lut[NC * KC * OF];
__device__ unsigned char g_idx[MAXTOK * NC];

// ---- packed f32x2 helpers --------------------------------------------------
__device__ __forceinline__ ull pk2(float x, float y) {
    ull r; asm("mov.b64 %0, {%1,%2};" : "=l"(r) : "f"(x), "f"(y)); return r;
}
__device__ __forceinline__ void upk2(ull v, float& x, float& y) {
    asm("mov.b64 {%0,%1}, %2;" : "=f"(x), "=f"(y) : "l"(v));
}
__device__ __forceinline__ ull fma2(ull a, ull b, ull c) {
    ull d; asm("fma.rn.f32x2 %0, %1, %2, %3;" : "=l"(d) : "l"(a), "l"(b), "l"(c)); return d;
}
__device__ __forceinline__ void lds_v2u64(ull& a, ull& b, const float* p) {
    asm("{ .reg .u64 t; cvta.to.shared.u64 t, %2; ld.shared.v2.u64 {%0,%1}, [t]; }"
        : "=l"(a), "=l"(b) : "l"(p));
}

// smem layout for idx (floats)
#define XS_STRIDE 132
#define IDX_XS    (128 * XS_STRIDE)          // 16896
#define IDX_CST   (DSUB * KC)                // 2048
#define IDX_RED   (3 * 128 * 17)             // 6528
#define IDX_C2P   128
#define IDX_C2S   16
#define IDX_FLOATS (IDX_XS + IDX_CST + IDX_RED + IDX_C2P + IDX_C2S)

// ---------------------------------------------------------------------------
// K2: idx[token][c] = argmin_k ( c2[k] - 2 * <x_sub, cent_k> )
// v6: 512 threads, 128 tokens, d split 4 ways (quarter = tid>>7, 32 d each).
// 2 CTAs/SM x 16 warps = 32 warps/SM (2x R8) with 1/4-length dependency
// chains -> latency finally hidden. Plain C++ loads (ptxas schedules; the
// R9 asm-immediate experiment proved hand addressing is a regression).
// Indices invariant under reduction-order change via fp64 near-tie recheck.
// ---------------------------------------------------------------------------
__global__ __launch_bounds__(512, 2) void idx_kernel(const float* __restrict__ x,
                                                     const float* __restrict__ cent)
{
    extern __shared__ float sm[];
    float* xs  = sm;                     // [128][XS_STRIDE]
    float* cst = sm + IDX_XS;            // [DSUB][KC]
    float* red = cst + IDX_CST;          // [3][128][17]
    float* c2p = red + IDX_RED;          // [16][8]
    float* c2s = c2p + IDX_C2P;          // [16]

    const int c   = blockIdx.y;
    const int tb  = blockIdx.x * 128;
    const int tid = threadIdx.x;

    // stage x tile: one 8-deep batch of independent LDG.128 per thread.
    {
        float4 buf[8];
#pragma unroll
        for (int j = 0; j < 8; j++) {
            int i   = tid + j * 512;
            int row = i >> 5;
            int col = (i & 31) * 4;
            buf[j] = *(const float4*)&x[(size_t)(tb + row) * INF + c * DSUB + col];
        }
#pragma unroll
        for (int j = 0; j < 8; j++) {
            int i   = tid + j * 512;
            int row = i >> 5;
            int col = (i & 31) * 4;
            *(float4*)&xs[row * XS_STRIDE + col] = buf[j];
        }
    }
    for (int i = tid; i < KC * DSUB; i += 512) {
        int k = i >> 7, d = i & 127;
        cst[d * KC + k] = cent[(c * KC + k) * DSUB + d];
    }
    __syncthreads();

    if (tid < 128) {
        int k = tid >> 3, part = tid & 7;
        float s = 0.f;
        for (int d = part * 16; d < part * 16 + 16; d++) {
            float cv = cst[d * KC + k];
            s = fmaf(cv, cv, s);
        }
        c2p[k * 8 + part] = s;
    }
    __syncthreads();
    if (tid < 16) {
        float s = 0.f;
        for (int p = 0; p < 8; p++) s += c2p[tid * 8 + p];
        c2s[tid] = s;
    }
    __syncthreads();

    const int token = tid & 127;
    const int q     = tid >> 7;          // d-quarter 0..3
    const int dbase = q * 32;

    float acc[KC];
#pragma unroll
    for (int k = 0; k < KC; k++) acc[k] = 0.f;

    const float* xr = &xs[token * XS_STRIDE];
    for (int d0 = dbase; d0 < dbase + 32; d0 += 4) {
        float4 xq = *(const float4*)&xr[d0];
        float xv4[4] = {xq.x, xq.y, xq.z, xq.w};
#pragma unroll
        for (int j = 0; j < 4; j++) {
            float xv = xv4[j];
            const float4* cp = (const float4*)&cst[(d0 + j) * KC];
            float4 c0 = cp[0], c1 = cp[1], c2v = cp[2], c3 = cp[3];
            acc[0]  = fmaf(xv, c0.x, acc[0]);   acc[1]  = fmaf(xv, c0.y, acc[1]);
            acc[2]  = fmaf(xv, c0.z, acc[2]);   acc[3]  = fmaf(xv, c0.w, acc[3]);
            acc[4]  = fmaf(xv, c1.x, acc[4]);   acc[5]  = fmaf(xv, c1.y, acc[5]);
            acc[6]  = fmaf(xv, c1.z, acc[6]);   acc[7]  = fmaf(xv, c1.w, acc[7]);
            acc[8]  = fmaf(xv, c2v.x, acc[8]);  acc[9]  = fmaf(xv, c2v.y, acc[9]);
            acc[10] = fmaf(xv, c2v.z, acc[10]); acc[11] = fmaf(xv, c2v.w, acc[11]);
            acc[12] = fmaf(xv, c3.x, acc[12]);  acc[13] = fmaf(xv, c3.y, acc[13]);
            acc[14] = fmaf(xv, c3.z, acc[14]);  acc[15] = fmaf(xv, c3.w, acc[15]);
        }
    }

    if (q != 0) {
#pragma unroll
        for (int k = 0; k < KC; k++)
            red[((q - 1) * 128 + token) * 17 + k] = acc[k];
    }
    __syncthreads();
    if (q == 0) {
        float best = 1e30f, second = 1e30f;
        int bi = 0, si = 0;
#pragma unroll
        for (int k = 0; k < KC; k++) {
            float dot = acc[k]
                      + red[(0 * 128 + token) * 17 + k]
                      + red[(1 * 128 + token) * 17 + k]
                      + red[(2 * 128 + token) * 17 + k];
            float v = c2s[k] - 2.f * dot;
            if (v < best)        { second = best; si = bi; best = v; bi = k; }
            else if (v < second) { second = v; si = k; }
        }
        if (second - best < 1e-3f) {
            double vb = 0.0, vs = 0.0;
            for (int d = 0; d < DSUB; d++) {
                double xv = (double)xr[d];
                double cb = (double)cst[d * KC + bi];
                double cs = (double)cst[d * KC + si];
                vb += cb * (cb - 2.0 * xv);
                vs += cs * (cs - 2.0 * xv);
            }
            if (vs < vb || (vs == vb && si < bi)) bi = si;
        }
        g_idx[(size_t)(tb + token) * NC + c] = (unsigned char)bi;
    }
}

// ---------------------------------------------------------------------------
// K1: lut — EXACT Round-8 version (the one inside the 91.2us best config).
// ---------------------------------------------------------------------------
__global__ __launch_bounds__(512) void lut_kernel(const float* __restrict__ cent,
                                                  const float* __restrict__ weight)
{
    __shared__ float cst[DSUB * KC];
    __shared__ float red[3][KC][128];

    const int c   = blockIdx.y;
    const int tid = threadIdx.x;
    const int dq  = tid >> 7;
    const int col = tid & 127;

    for (int i = tid; i < KC * DSUB; i += 512) {
        int k = i >> 7, d = i & 127;
        cst[d * KC + k] = cent[(c * KC + k) * DSUB + d];
    }
    __syncthreads();

    const int o = blockIdx.x * 128 + col;
    const float* wp = weight + (size_t)c * DSUB * OF + o + (size_t)(dq * 32) * OF;

    ull acc[8];
#pragma unroll
    for (int p = 0; p < 8; p++) acc[p] = 0ull;

#pragma unroll
    for (int half = 0; half < 2; half++) {
        float w[16];
#pragma unroll
        for (int i = 0; i < 16; i++) w[i] = wp[(size_t)(half * 16 + i) * OF];
#pragma unroll
        for (int i = 0; i < 16; i++) {
            ull wv = pk2(w[i], w[i]);
            const float* cp = &cst[(dq * 32 + half * 16 + i) * KC];
            ull a0, a1, a2, a3;
            lds_v2u64(a0, a1, cp);
            lds_v2u64(a2, a3, cp + 8);
            acc[0] = fma2(a0, wv, acc[0]);
            acc[1] = fma2(a1, wv, acc[1]);
            acc[2] = fma2(a2, wv, acc[2]);
            acc[3] = fma2(a3, wv, acc[3]);
            lds_v2u64(a0, a1, cp + 4);
            acc[4] = fma2(a0, wv, acc[4]);
            acc[5] = fma2(a1, wv, acc[5]);
            lds_v2u64(a2, a3, cp + 12);
            acc[6] = fma2(a2, wv, acc[6]);
            acc[7] = fma2(a3, wv, acc[7]);
        }
    }

    const int kmap[8] = {0, 1, 4, 5, 2, 3, 6, 7};

    if (dq != 0) {
#pragma unroll
        for (int p = 0; p < 8; p++) {
            float v0, v1; upk2(acc[p], v0, v1);
            int kp = kmap[p];
            red[dq - 1][kp * 2 + 0][col] = v0;
            red[dq - 1][kp * 2 + 1][col] = v1;
        }
    }
    __syncthreads();
    if (dq == 0) {
#pragma unroll
        for (int p = 0; p < 8; p++) {
            float v0, v1; upk2(acc[p], v0, v1);
            int k0 = kmap[p] * 2, k1 = k0 + 1;
            v0 = v0 + red[0][k0][col] + red[1][k0][col] + red[2][k0][col];
            v1 = v1 + red[0][k1][col] + red[1][k1][col] + red[2][k1][col];
            g_lut[(size_t)(c * KC + k0) * OF + o] = v0;
            g_lut[(size_t)(c * KC + k1) * OF + o] = v1;
        }
    }
}

// ---------------------------------------------------------------------------
// K3: gather — EXACT Round-4 version (unchanged).
// ---------------------------------------------------------------------------
__global__ __launch_bounds__(256) void gather_kernel(float* __restrict__ out,
                                                     const float* __restrict__ bias)
{
    extern __shared__ float sm[];
    float*         lut_s = sm;
    unsigned char* idx_s = (unsigned char*)(sm + NC * KC * 32);

    const int ob  = blockIdx.x * 32;
    const int tb  = blockIdx.y * 256;
    const int tid = threadIdx.x;

    for (int i = tid; i < NC * KC * 32 / 4; i += 256) {
        int row = i >> 3;
        int col = (i & 7) * 4;
        float4 v = *(const float4*)&g_lut[(size_t)row * OF + ob + col];
        *(float4*)&lut_s[row * 32 + col] = v;
    }
    {
        const uint4* src = (const uint4*)&g_idx[(size_t)tb * NC];
        uint4* dst = (uint4*)idx_s;
        for (int i = tid; i < (256 * NC) / 16; i += 256) dst[i] = src[i];
    }
    __syncthreads();

    const int oi = tid & 31;
    const int tg = tid >> 5;
    const float bv = bias[ob + oi];

    for (int t = tg; t < 256; t += 8) {
        uint4 a = *(const uint4*)&idx_s[t * NC];
        uint4 b = *(const uint4*)&idx_s[t * NC + 16];
        unsigned int iw[8] = {a.x, a.y, a.z, a.w, b.x, b.y, b.z, b.w};
        float s0 = 0.f, s1 = 0.f;
#pragma unroll
        for (int c = 0; c < NC; c++) {
            unsigned int k = (iw[c >> 2] >> ((c & 3) * 8)) & 0xFFu;
            float v = lut_s[(c * KC + k) * 32 + oi];
            if (c & 1) s1 += v;
            else       s0 += v;
        }
        out[(size_t)(tb + t) * OF + ob + oi] = s0 + s1 + bv;
    }
}

// ---------------------------------------------------------------------------
extern "C" void kernel_launch(void* const* d_in, const int* in_sizes, int n_in,
                              void* d_out, int out_size)
{
    const float* x      = (const float*)d_in[0];
    const float* cent   = (const float*)d_in[1];
    const float* weight = (const float*)d_in[2];
    const float* bias   = (const float*)d_in[4];
    float* out = (float*)d_out;

    const int ntok = in_sizes[0] / INF;

    const int IDX_SMEM = IDX_FLOATS * (int)sizeof(float);   // ~102 KB -> 2 CTAs/SM
    const int G_SMEM   = NC * KC * 32 * (int)sizeof(float) + 256 * NC;

    cudaFuncSetAttribute(idx_kernel,    cudaFuncAttributeMaxDynamicSharedMemorySize, IDX_SMEM);
    cudaFuncSetAttribute(gather_kernel, cudaFuncAttributeMaxDynamicSharedMemorySize, G_SMEM);

    idx_kernel<<<dim3(ntok / 128, NC), 512, IDX_SMEM>>>(x, cent);
    lut_kernel<<<dim3(OF / 128, NC), 512>>>(cent, weight);
    gather_kernel<<<dim3(OF / 32, ntok / 256), 256, G_SMEM>>>(out, bias);
}

// round 11
// speedup vs baseline: 1.7237x; 1.0838x over previous
#include <cuda_runtime.h>
#include <stdint.h>

#define NC    32
#define KC    16
#define DSUB  128
#define INF   4096
#define OF    2048
#define MAXTOK 2048

typedef unsigned long long ull;

__device__ float         g_lut[NC * KC * OF];
__device__ unsigned char g_idx[MAXTOK * NC];

// ---- packed f32x2 helpers --------------------------------------------------
__device__ __forceinline__ ull pk2(float x, float y) {
    ull r; asm("mov.b64 %0, {%1,%2};" : "=l"(r) : "f"(x), "f"(y)); return r;
}
__device__ __forceinline__ void upk2(ull v, float& x, float& y) {
    asm("mov.b64 {%0,%1}, %2;" : "=f"(x), "=f"(y) : "l"(v));
}
__device__ __forceinline__ ull fma2(ull a, ull b, ull c) {
    ull d; asm("fma.rn.f32x2 %0, %1, %2, %3;" : "=l"(d) : "l"(a), "l"(b), "l"(c)); return d;
}
__device__ __forceinline__ void lds_v2u64(ull& a, ull& b, const float* p) {
    asm("{ .reg .u64 t; cvta.to.shared.u64 t, %2; ld.shared.v2.u64 {%0,%1}, [t]; }"
        : "=l"(a), "=l"(b) : "l"(p));
}

// smem layout for the idx half (floats)
#define XS_STRIDE 132
#define IDX_XS    (128 * XS_STRIDE)          // 16896
#define IDX_CST   (DSUB * KC)                // 2048
#define IDX_RED   (3 * 128 * 17)             // 6528
#define IDX_C2P   128
#define IDX_C2S   16
#define IDX_FLOATS (IDX_XS + IDX_CST + IDX_RED + IDX_C2P + IDX_C2S)   // 25616 fl ≈ 102 KB

// ---------------------------------------------------------------------------
// Fused kernel: even blocks = idx work (EXACT R10 body), odd blocks = lut
// work (EXACT R8 body, smem aliased into the dynamic block). The two work
// types have complementary bottlenecks (idx: smem/FFMA latency chain with
// idle DRAM; lut: DRAM streaming with idle math) — interleaving them on each
// SM overlaps the phases that previously ran back-to-back.
// ---------------------------------------------------------------------------
__global__ __launch_bounds__(512, 2) void fused_idx_lut(const float* __restrict__ x,
                                                        const float* __restrict__ cent,
                                                        const float* __restrict__ weight)
{
    extern __shared__ float sm[];
    const int id = blockIdx.x;
    const int w  = id >> 1;

    if ((id & 1) == 0) {
        // ================= idx body (R10, verbatim) =================
        float* xs  = sm;                     // [128][XS_STRIDE]
        float* cst = sm + IDX_XS;            // [DSUB][KC]
        float* red = cst + IDX_CST;          // [3][128][17]
        float* c2p = red + IDX_RED;          // [16][8]
        float* c2s = c2p + IDX_C2P;          // [16]

        const int c   = w & 31;
        const int tb  = (w >> 5) * 128;
        const int tid = threadIdx.x;

        {
            float4 buf[8];
#pragma unroll
            for (int j = 0; j < 8; j++) {
                int i   = tid + j * 512;
                int row = i >> 5;
                int col = (i & 31) * 4;
                buf[j] = *(const float4*)&x[(size_t)(tb + row) * INF + c * DSUB + col];
            }
#pragma unroll
            for (int j = 0; j < 8; j++) {
                int i   = tid + j * 512;
                int row = i >> 5;
                int col = (i & 31) * 4;
                *(float4*)&xs[row * XS_STRIDE + col] = buf[j];
            }
        }
        for (int i = tid; i < KC * DSUB; i += 512) {
            int k = i >> 7, d = i & 127;
            cst[d * KC + k] = cent[(c * KC + k) * DSUB + d];
        }
        __syncthreads();

        if (tid < 128) {
            int k = tid >> 3, part = tid & 7;
            float s = 0.f;
            for (int d = part * 16; d < part * 16 + 16; d++) {
                float cv = cst[d * KC + k];
                s = fmaf(cv, cv, s);
            }
            c2p[k * 8 + part] = s;
        }
        __syncthreads();
        if (tid < 16) {
            float s = 0.f;
            for (int p = 0; p < 8; p++) s += c2p[tid * 8 + p];
            c2s[tid] = s;
        }
        __syncthreads();

        const int token = tid & 127;
        const int q     = tid >> 7;
        const int dbase = q * 32;

        float acc[KC];
#pragma unroll
        for (int k = 0; k < KC; k++) acc[k] = 0.f;

        const float* xr = &xs[token * XS_STRIDE];
        for (int d0 = dbase; d0 < dbase + 32; d0 += 4) {
            float4 xq = *(const float4*)&xr[d0];
            float xv4[4] = {xq.x, xq.y, xq.z, xq.w};
#pragma unroll
            for (int j = 0; j < 4; j++) {
                float xv = xv4[j];
                const float4* cp = (const float4*)&cst[(d0 + j) * KC];
                float4 c0 = cp[0], c1 = cp[1], c2v = cp[2], c3 = cp[3];
                acc[0]  = fmaf(xv, c0.x, acc[0]);   acc[1]  = fmaf(xv, c0.y, acc[1]);
                acc[2]  = fmaf(xv, c0.z, acc[2]);   acc[3]  = fmaf(xv, c0.w, acc[3]);
                acc[4]  = fmaf(xv, c1.x, acc[4]);   acc[5]  = fmaf(xv, c1.y, acc[5]);
                acc[6]  = fmaf(xv, c1.z, acc[6]);   acc[7]  = fmaf(xv, c1.w, acc[7]);
                acc[8]  = fmaf(xv, c2v.x, acc[8]);  acc[9]  = fmaf(xv, c2v.y, acc[9]);
                acc[10] = fmaf(xv, c2v.z, acc[10]); acc[11] = fmaf(xv, c2v.w, acc[11]);
                acc[12] = fmaf(xv, c3.x, acc[12]);  acc[13] = fmaf(xv, c3.y, acc[13]);
                acc[14] = fmaf(xv, c3.z, acc[14]);  acc[15] = fmaf(xv, c3.w, acc[15]);
            }
        }

        if (q != 0) {
#pragma unroll
            for (int k = 0; k < KC; k++)
                red[((q - 1) * 128 + token) * 17 + k] = acc[k];
        }
        __syncthreads();
        if (q == 0) {
            float best = 1e30f, second = 1e30f;
            int bi = 0, si = 0;
#pragma unroll
            for (int k = 0; k < KC; k++) {
                float dot = acc[k]
                          + red[(0 * 128 + token) * 17 + k]
                          + red[(1 * 128 + token) * 17 + k]
                          + red[(2 * 128 + token) * 17 + k];
                float v = c2s[k] - 2.f * dot;
                if (v < best)        { second = best; si = bi; best = v; bi = k; }
                else if (v < second) { second = v; si = k; }
            }
            if (second - best < 1e-3f) {
                double vb = 0.0, vs = 0.0;
                for (int d = 0; d < DSUB; d++) {
                    double xv = (double)xr[d];
                    double cb = (double)cst[d * KC + bi];
                    double cs = (double)cst[d * KC + si];
                    vb += cb * (cb - 2.0 * xv);
                    vs += cs * (cs - 2.0 * xv);
                }
                if (vs < vb || (vs == vb && si < bi)) bi = si;
            }
            g_idx[(size_t)(tb + token) * NC + c] = (unsigned char)bi;
        }
    } else {
        // ================= lut body (R8, smem aliased) =================
        float* cst = sm;                     // [DSUB][KC]         (2048 fl)
        float* red = sm + IDX_CST;           // [3][KC][128]       (6144 fl)

        const int c   = w & 31;
        const int tid = threadIdx.x;
        const int dq  = tid >> 7;
        const int col = tid & 127;

        for (int i = tid; i < KC * DSUB; i += 512) {
            int k = i >> 7, d = i & 127;
            cst[d * KC + k] = cent[(c * KC + k) * DSUB + d];
        }
        __syncthreads();

        const int o = (w >> 5) * 128 + col;
        const float* wp = weight + (size_t)c * DSUB * OF + o + (size_t)(dq * 32) * OF;

        ull acc[8];
#pragma unroll
        for (int p = 0; p < 8; p++) acc[p] = 0ull;

#pragma unroll
        for (int half = 0; half < 2; half++) {
            float wv_[16];
#pragma unroll
            for (int i = 0; i < 16; i++) wv_[i] = wp[(size_t)(half * 16 + i) * OF];
#pragma unroll
            for (int i = 0; i < 16; i++) {
                ull wv = pk2(wv_[i], wv_[i]);
                const float* cp = &cst[(dq * 32 + half * 16 + i) * KC];
                ull a0, a1, a2, a3;
                lds_v2u64(a0, a1, cp);
                lds_v2u64(a2, a3, cp + 8);
                acc[0] = fma2(a0, wv, acc[0]);
                acc[1] = fma2(a1, wv, acc[1]);
                acc[2] = fma2(a2, wv, acc[2]);
                acc[3] = fma2(a3, wv, acc[3]);
                lds_v2u64(a0, a1, cp + 4);
                acc[4] = fma2(a0, wv, acc[4]);
                acc[5] = fma2(a1, wv, acc[5]);
                lds_v2u64(a2, a3, cp + 12);
                acc[6] = fma2(a2, wv, acc[6]);
                acc[7] = fma2(a3, wv, acc[7]);
            }
        }

        const int kmap[8] = {0, 1, 4, 5, 2, 3, 6, 7};

        if (dq != 0) {
#pragma unroll
            for (int p = 0; p < 8; p++) {
                float v0, v1; upk2(acc[p], v0, v1);
                int kp = kmap[p];
                red[(((dq - 1) * KC) + kp * 2 + 0) * 128 + col] = v0;
                red[(((dq - 1) * KC) + kp * 2 + 1) * 128 + col] = v1;
            }
        }
        __syncthreads();
        if (dq == 0) {
#pragma unroll
            for (int p = 0; p < 8; p++) {
                float v0, v1; upk2(acc[p], v0, v1);
                int k0 = kmap[p] * 2, k1 = k0 + 1;
                v0 = v0 + red[(0 * KC + k0) * 128 + col]
                        + red[(1 * KC + k0) * 128 + col]
                        + red[(2 * KC + k0) * 128 + col];
                v1 = v1 + red[(0 * KC + k1) * 128 + col]
                        + red[(1 * KC + k1) * 128 + col]
                        + red[(2 * KC + k1) * 128 + col];
                g_lut[(size_t)(c * KC + k0) * OF + o] = v0;
                g_lut[(size_t)(c * KC + k1) * OF + o] = v1;
            }
        }
    }
}

// ---------------------------------------------------------------------------
// K3: gather — EXACT Round-4 version (unchanged).
// ---------------------------------------------------------------------------
__global__ __launch_bounds__(256) void gather_kernel(float* __restrict__ out,
                                                     const float* __restrict__ bias)
{
    extern __shared__ float sm[];
    float*         lut_s = sm;
    unsigned char* idx_s = (unsigned char*)(sm + NC * KC * 32);

    const int ob  = blockIdx.x * 32;
    const int tb  = blockIdx.y * 256;
    const int tid = threadIdx.x;

    for (int i = tid; i < NC * KC * 32 / 4; i += 256) {
        int row = i >> 3;
        int col = (i & 7) * 4;
        float4 v = *(const float4*)&g_lut[(size_t)row * OF + ob + col];
        *(float4*)&lut_s[row * 32 + col] = v;
    }
    {
        const uint4* src = (const uint4*)&g_idx[(size_t)tb * NC];
        uint4* dst = (uint4*)idx_s;
        for (int i = tid; i < (256 * NC) / 16; i += 256) dst[i] = src[i];
    }
    __syncthreads();

    const int oi = tid & 31;
    const int tg = tid >> 5;
    const float bv = bias[ob + oi];

    for (int t = tg; t < 256; t += 8) {
        uint4 a = *(const uint4*)&idx_s[t * NC];
        uint4 b = *(const uint4*)&idx_s[t * NC + 16];
        unsigned int iw[8] = {a.x, a.y, a.z, a.w, b.x, b.y, b.z, b.w};
        float s0 = 0.f, s1 = 0.f;
#pragma unroll
        for (int c = 0; c < NC; c++) {
            unsigned int k = (iw[c >> 2] >> ((c & 3) * 8)) & 0xFFu;
            float v = lut_s[(c * KC + k) * 32 + oi];
            if (c & 1) s1 += v;
            else       s0 += v;
        }
        out[(size_t)(tb + t) * OF + ob + oi] = s0 + s1 + bv;
    }
}

// ---------------------------------------------------------------------------
extern "C" void kernel_launch(void* const* d_in, const int* in_sizes, int n_in,
                              void* d_out, int out_size)
{
    const float* x      = (const float*)d_in[0];
    const float* cent   = (const float*)d_in[1];
    const float* weight = (const float*)d_in[2];
    const float* bias   = (const float*)d_in[4];
    float* out = (float*)d_out;

    const int ntok = in_sizes[0] / INF;

    const int FUSED_SMEM = IDX_FLOATS * (int)sizeof(float);   // ~102 KB -> 2 CTAs/SM
    const int G_SMEM     = NC * KC * 32 * (int)sizeof(float) + 256 * NC;

    cudaFuncSetAttribute(fused_idx_lut, cudaFuncAttributeMaxDynamicSharedMemorySize, FUSED_SMEM);
    cudaFuncSetAttribute(gather_kernel, cudaFuncAttributeMaxDynamicSharedMemorySize, G_SMEM);

    // even blocks: idx work ((ntok/128)*NC items); odd blocks: lut work (16*NC).
    // For ntok=2048 both are 512 — perfectly interleaved.
    const int nblk = (ntok / 128) * NC;      // 512
    fused_idx_lut<<<nblk * 2, 512, FUSED_SMEM>>>(x, cent, weight);
    gather_kernel<<<dim3(OF / 32, ntok / 256), 256, G_SMEM>>>(out, bias);
}

// round 12
// speedup vs baseline: 1.7437x; 1.0116x over previous
#include <cuda_runtime.h>
#include <stdint.h>

#define NC    32
#define KC    16
#define DSUB  128
#define INF   4096
#define OF    2048
#define MAXTOK 2048

typedef unsigned long long ull;

__device__ float         g_lut[NC * KC * OF];
__device__ unsigned char g_idx[MAXTOK * NC];

// ---- packed f32x2 helpers --------------------------------------------------
__device__ __forceinline__ ull pk2(float x, float y) {
    ull r; asm("mov.b64 %0, {%1,%2};" : "=l"(r) : "f"(x), "f"(y)); return r;
}
__device__ __forceinline__ void upk2(ull v, float& x, float& y) {
    asm("mov.b64 {%0,%1}, %2;" : "=f"(x), "=f"(y) : "l"(v));
}
__device__ __forceinline__ ull fma2(ull a, ull b, ull c) {
    ull d; asm("fma.rn.f32x2 %0, %1, %2, %3;" : "=l"(d) : "l"(a), "l"(b), "l"(c)); return d;
}
__device__ __forceinline__ void lds_v2u64(ull& a, ull& b, const float* p) {
    asm("{ .reg .u64 t; cvta.to.shared.u64 t, %2; ld.shared.v2.u64 {%0,%1}, [t]; }"
        : "=l"(a), "=l"(b) : "l"(p));
}

// smem layout for the idx half (floats)
#define XS_STRIDE 132
#define IDX_XS    (128 * XS_STRIDE)          // 16896
#define IDX_CST   (DSUB * KC)                // 2048
#define IDX_RED   (3 * 128 * 17)             // 6528
#define IDX_C2P   128
#define IDX_C2S   16
#define IDX_FLOATS (IDX_XS + IDX_CST + IDX_RED + IDX_C2P + IDX_C2S)

// ---------------------------------------------------------------------------
// Fused kernel — EXACT Round-11 version (unchanged this round).
// ---------------------------------------------------------------------------
__global__ __launch_bounds__(512, 2) void fused_idx_lut(const float* __restrict__ x,
                                                        const float* __restrict__ cent,
                                                        const float* __restrict__ weight)
{
    extern __shared__ float sm[];
    const int id = blockIdx.x;
    const int w  = id >> 1;

    if ((id & 1) == 0) {
        float* xs  = sm;
        float* cst = sm + IDX_XS;
        float* red = cst + IDX_CST;
        float* c2p = red + IDX_RED;
        float* c2s = c2p + IDX_C2P;

        const int c   = w & 31;
        const int tb  = (w >> 5) * 128;
        const int tid = threadIdx.x;

        {
            float4 buf[8];
#pragma unroll
            for (int j = 0; j < 8; j++) {
                int i   = tid + j * 512;
                int row = i >> 5;
                int col = (i & 31) * 4;
                buf[j] = *(const float4*)&x[(size_t)(tb + row) * INF + c * DSUB + col];
            }
#pragma unroll
            for (int j = 0; j < 8; j++) {
                int i   = tid + j * 512;
                int row = i >> 5;
                int col = (i & 31) * 4;
                *(float4*)&xs[row * XS_STRIDE + col] = buf[j];
            }
        }
        for (int i = tid; i < KC * DSUB; i += 512) {
            int k = i >> 7, d = i & 127;
            cst[d * KC + k] = cent[(c * KC + k) * DSUB + d];
        }
        __syncthreads();

        if (tid < 128) {
            int k = tid >> 3, part = tid & 7;
            float s = 0.f;
            for (int d = part * 16; d < part * 16 + 16; d++) {
                float cv = cst[d * KC + k];
                s = fmaf(cv, cv, s);
            }
            c2p[k * 8 + part] = s;
        }
        __syncthreads();
        if (tid < 16) {
            float s = 0.f;
            for (int p = 0; p < 8; p++) s += c2p[tid * 8 + p];
            c2s[tid] = s;
        }
        __syncthreads();

        const int token = tid & 127;
        const int q     = tid >> 7;
        const int dbase = q * 32;

        float acc[KC];
#pragma unroll
        for (int k = 0; k < KC; k++) acc[k] = 0.f;

        const float* xr = &xs[token * XS_STRIDE];
        for (int d0 = dbase; d0 < dbase + 32; d0 += 4) {
            float4 xq = *(const float4*)&xr[d0];
            float xv4[4] = {xq.x, xq.y, xq.z, xq.w};
#pragma unroll
            for (int j = 0; j < 4; j++) {
                float xv = xv4[j];
                const float4* cp = (const float4*)&cst[(d0 + j) * KC];
                float4 c0 = cp[0], c1 = cp[1], c2v = cp[2], c3 = cp[3];
                acc[0]  = fmaf(xv, c0.x, acc[0]);   acc[1]  = fmaf(xv, c0.y, acc[1]);
                acc[2]  = fmaf(xv, c0.z, acc[2]);   acc[3]  = fmaf(xv, c0.w, acc[3]);
                acc[4]  = fmaf(xv, c1.x, acc[4]);   acc[5]  = fmaf(xv, c1.y, acc[5]);
                acc[6]  = fmaf(xv, c1.z, acc[6]);   acc[7]  = fmaf(xv, c1.w, acc[7]);
                acc[8]  = fmaf(xv, c2v.x, acc[8]);  acc[9]  = fmaf(xv, c2v.y, acc[9]);
                acc[10] = fmaf(xv, c2v.z, acc[10]); acc[11] = fmaf(xv, c2v.w, acc[11]);
                acc[12] = fmaf(xv, c3.x, acc[12]);  acc[13] = fmaf(xv, c3.y, acc[13]);
                acc[14] = fmaf(xv, c3.z, acc[14]);  acc[15] = fmaf(xv, c3.w, acc[15]);
            }
        }

        if (q != 0) {
#pragma unroll
            for (int k = 0; k < KC; k++)
                red[((q - 1) * 128 + token) * 17 + k] = acc[k];
        }
        __syncthreads();
        if (q == 0) {
            float best = 1e30f, second = 1e30f;
            int bi = 0, si = 0;
#pragma unroll
            for (int k = 0; k < KC; k++) {
                float dot = acc[k]
                          + red[(0 * 128 + token) * 17 + k]
                          + red[(1 * 128 + token) * 17 + k]
                          + red[(2 * 128 + token) * 17 + k];
                float v = c2s[k] - 2.f * dot;
                if (v < best)        { second = best; si = bi; best = v; bi = k; }
                else if (v < second) { second = v; si = k; }
            }
            if (second - best < 1e-3f) {
                double vb = 0.0, vs = 0.0;
                for (int d = 0; d < DSUB; d++) {
                    double xv = (double)xr[d];
                    double cb = (double)cst[d * KC + bi];
                    double cs = (double)cst[d * KC + si];
                    vb += cb * (cb - 2.0 * xv);
                    vs += cs * (cs - 2.0 * xv);
                }
                if (vs < vb || (vs == vb && si < bi)) bi = si;
            }
            g_idx[(size_t)(tb + token) * NC + c] = (unsigned char)bi;
        }
    } else {
        float* cst = sm;
        float* red = sm + IDX_CST;

        const int c   = w & 31;
        const int tid = threadIdx.x;
        const int dq  = tid >> 7;
        const int col = tid & 127;

        for (int i = tid; i < KC * DSUB; i += 512) {
            int k = i >> 7, d = i & 127;
            cst[d * KC + k] = cent[(c * KC + k) * DSUB + d];
        }
        __syncthreads();

        const int o = (w >> 5) * 128 + col;
        const float* wp = weight + (size_t)c * DSUB * OF + o + (size_t)(dq * 32) * OF;

        ull acc[8];
#pragma unroll
        for (int p = 0; p < 8; p++) acc[p] = 0ull;

#pragma unroll
        for (int half = 0; half < 2; half++) {
            float wv_[16];
#pragma unroll
            for (int i = 0; i < 16; i++) wv_[i] = wp[(size_t)(half * 16 + i) * OF];
#pragma unroll
            for (int i = 0; i < 16; i++) {
                ull wv = pk2(wv_[i], wv_[i]);
                const float* cp = &cst[(dq * 32 + half * 16 + i) * KC];
                ull a0, a1, a2, a3;
                lds_v2u64(a0, a1, cp);
                lds_v2u64(a2, a3, cp + 8);
                acc[0] = fma2(a0, wv, acc[0]);
                acc[1] = fma2(a1, wv, acc[1]);
                acc[2] = fma2(a2, wv, acc[2]);
                acc[3] = fma2(a3, wv, acc[3]);
                lds_v2u64(a0, a1, cp + 4);
                acc[4] = fma2(a0, wv, acc[4]);
                acc[5] = fma2(a1, wv, acc[5]);
                lds_v2u64(a2, a3, cp + 12);
                acc[6] = fma2(a2, wv, acc[6]);
                acc[7] = fma2(a3, wv, acc[7]);
            }
        }

        const int kmap[8] = {0, 1, 4, 5, 2, 3, 6, 7};

        if (dq != 0) {
#pragma unroll
            for (int p = 0; p < 8; p++) {
                float v0, v1; upk2(acc[p], v0, v1);
                int kp = kmap[p];
                red[(((dq - 1) * KC) + kp * 2 + 0) * 128 + col] = v0;
                red[(((dq - 1) * KC) + kp * 2 + 1) * 128 + col] = v1;
            }
        }
        __syncthreads();
        if (dq == 0) {
#pragma unroll
            for (int p = 0; p < 8; p++) {
                float v0, v1; upk2(acc[p], v0, v1);
                int k0 = kmap[p] * 2, k1 = k0 + 1;
                v0 = v0 + red[(0 * KC + k0) * 128 + col]
                        + red[(1 * KC + k0) * 128 + col]
                        + red[(2 * KC + k0) * 128 + col];
                v1 = v1 + red[(0 * KC + k1) * 128 + col]
                        + red[(1 * KC + k1) * 128 + col]
                        + red[(2 * KC + k1) * 128 + col];
                g_lut[(size_t)(c * KC + k0) * OF + o] = v0;
                g_lut[(size_t)(c * KC + k1) * OF + o] = v1;
            }
        }
    }
}

// ---------------------------------------------------------------------------
// K3: gather v2 — thread = (o-quad, token-group).
// Per (t,c): 1 extract + 1 shift-add + 1 LDS.128 + 4 FADD for 4 outputs
// (~2 instr/output vs R4's ~4.5). LDS.128 phases are conflict-free: 8 lanes
// of one token read one full 128B row. Per-column accumulation order is
// identical to R4 (even-c sum, odd-c sum, (s0+s1)+bias) -> same bits.
// ---------------------------------------------------------------------------
__global__ __launch_bounds__(256, 3) void gather_kernel(float* __restrict__ out,
                                                        const float* __restrict__ bias)
{
    extern __shared__ float sm[];
    float*         lut_s = sm;                                  // [512][32] floats
    unsigned char* idx_s = (unsigned char*)(sm + NC * KC * 32); // 256*32 B

    const int ob  = blockIdx.x * 32;
    const int tb  = blockIdx.y * 256;
    const int tid = threadIdx.x;

    for (int i = tid; i < NC * KC * 32 / 4; i += 256) {
        int row = i >> 3;
        int col = (i & 7) * 4;
        float4 v = *(const float4*)&g_lut[(size_t)row * OF + ob + col];
        *(float4*)&lut_s[row * 32 + col] = v;
    }
    {
        const uint4* src = (const uint4*)&g_idx[(size_t)tb * NC];
        uint4* dst = (uint4*)idx_s;
        for (int i = tid; i < (256 * NC) / 16; i += 256) dst[i] = src[i];
    }
    __syncthreads();

    const int oq = tid & 7;    // o-quad: columns oq*4 .. oq*4+3
    const int tg = tid >> 3;   // token group 0..31
    const float4 bv = *(const float4*)&bias[ob + oq * 4];
    const float* lut_q = lut_s + oq * 4;   // quad base; row offset c*512+k*32 floats

    for (int t = tg; t < 256; t += 32) {
        uint4 a = *(const uint4*)&idx_s[t * NC];
        uint4 b = *(const uint4*)&idx_s[t * NC + 16];
        unsigned int iw[8] = {a.x, a.y, a.z, a.w, b.x, b.y, b.z, b.w};
        // per-column partial sums: x0..w0 = even c, x1..w1 = odd c
        float x0 = 0.f, y0 = 0.f, z0 = 0.f, w0 = 0.f;
        float x1 = 0.f, y1 = 0.f, z1 = 0.f, w1 = 0.f;
#pragma unroll
        for (int c = 0; c < NC; c++) {
            unsigned int k = (iw[c >> 2] >> ((c & 3) * 8)) & 0xFFu;
            // address: c*512 floats is a compile-time constant (folds into the
            // LDS immediate); only k*32 floats is dynamic.
            float4 v = *(const float4*)&lut_q[c * 512 + k * 32];
            if (c & 1) { x1 += v.x; y1 += v.y; z1 += v.z; w1 += v.w; }
            else       { x0 += v.x; y0 += v.y; z0 += v.z; w0 += v.w; }
        }
        float4 r;
        r.x = (x0 + x1) + bv.x;
        r.y = (y0 + y1) + bv.y;
        r.z = (z0 + z1) + bv.z;
        r.w = (w0 + w1) + bv.w;
        *(float4*)&out[(size_t)(tb + t) * OF + ob + oq * 4] = r;
    }
}

// ---------------------------------------------------------------------------
extern "C" void kernel_launch(void* const* d_in, const int* in_sizes, int n_in,
                              void* d_out, int out_size)
{
    const float* x      = (const float*)d_in[0];
    const float* cent   = (const float*)d_in[1];
    const float* weight = (const float*)d_in[2];
    const float* bias   = (const float*)d_in[4];
    float* out = (float*)d_out;

    const int ntok = in_sizes[0] / INF;

    const int FUSED_SMEM = IDX_FLOATS * (int)sizeof(float);
    const int G_SMEM     = NC * KC * 32 * (int)sizeof(float) + 256 * NC;

    cudaFuncSetAttribute(fused_idx_lut, cudaFuncAttributeMaxDynamicSharedMemorySize, FUSED_SMEM);
    cudaFuncSetAttribute(gather_kernel, cudaFuncAttributeMaxDynamicSharedMemorySize, G_SMEM);

    const int nblk = (ntok / 128) * NC;      // 512
    fused_idx_lut<<<nblk * 2, 512, FUSED_SMEM>>>(x, cent, weight);
    gather_kernel<<<dim3(OF / 32, ntok / 256), 256, G_SMEM>>>(out, bias);
}

// round 13
// speedup vs baseline: 1.8893x; 1.0835x over previous
#include <cuda_runtime.h>
#include <stdint.h>

#define NC    32
#define KC    16
#define DSUB  128
#define INF   4096
#define OF    2048
#define MAXTOK 2048

typedef unsigned long long ull;

__device__ float         g_lut[NC * KC * OF];
__device__ unsigned char g_idx[MAXTOK * NC];

// ---- packed f32x2 helpers --------------------------------------------------
__device__ __forceinline__ ull pk2(float x, float y) {
    ull r; asm("mov.b64 %0, {%1,%2};" : "=l"(r) : "f"(x), "f"(y)); return r;
}
__device__ __forceinline__ void upk2(ull v, float& x, float& y) {
    asm("mov.b64 {%0,%1}, %2;" : "=f"(x), "=f"(y) : "l"(v));
}
__device__ __forceinline__ ull fma2(ull a, ull b, ull c) {
    ull d; asm("fma.rn.f32x2 %0, %1, %2, %3;" : "=l"(d) : "l"(a), "l"(b), "l"(c)); return d;
}
__device__ __forceinline__ void lds_v2u64(ull& a, ull& b, const float* p) {
    asm("{ .reg .u64 t; cvta.to.shared.u64 t, %2; ld.shared.v2.u64 {%0,%1}, [t]; }"
        : "=l"(a), "=l"(b) : "l"(p));
}

// smem layout for the idx half (floats)
#define XS_STRIDE 132
#define IDX_XS    (128 * XS_STRIDE)          // 16896
#define IDX_CST   (DSUB * KC)                // 2048
#define IDX_RED   (3 * 128 * 17)             // 6528
#define IDX_C2P   128
#define IDX_C2S   16
#define IDX_FLOATS (IDX_XS + IDX_CST + IDX_RED + IDX_C2P + IDX_C2S)

#define ACC16(A, xv) do {                                              \
    A[0]  = fmaf(xv, c0.x, A[0]);   A[1]  = fmaf(xv, c0.y, A[1]);      \
    A[2]  = fmaf(xv, c0.z, A[2]);   A[3]  = fmaf(xv, c0.w, A[3]);      \
    A[4]  = fmaf(xv, c1.x, A[4]);   A[5]  = fmaf(xv, c1.y, A[5]);      \
    A[6]  = fmaf(xv, c1.z, A[6]);   A[7]  = fmaf(xv, c1.w, A[7]);      \
    A[8]  = fmaf(xv, c2v.x, A[8]);  A[9]  = fmaf(xv, c2v.y, A[9]);     \
    A[10] = fmaf(xv, c2v.z, A[10]); A[11] = fmaf(xv, c2v.w, A[11]);    \
    A[12] = fmaf(xv, c3.x, A[12]);  A[13] = fmaf(xv, c3.y, A[13]);     \
    A[14] = fmaf(xv, c3.z, A[14]);  A[15] = fmaf(xv, c3.w, A[15]);     \
} while (0)

// ---------------------------------------------------------------------------
// Fused kernel, v2: 256 threads/block, 2 work items per thread sharing the
// broadcast centroid loads (idx: tokens tp & tp+64; lut: cols col & col+64).
// Halves LDS issues per unit work and doubles per-warp FFMA ILP — targeting
// the "nothing saturated" latency regime both kernels measured in.
// All per-item accumulation chains keep their exact order -> same bits.
// ---------------------------------------------------------------------------
__global__ __launch_bounds__(256, 2) void fused_idx_lut(const float* __restrict__ x,
                                                        const float* __restrict__ cent,
                                                        const float* __restrict__ weight)
{
    extern __shared__ float sm[];
    const int id = blockIdx.x;
    const int w  = id >> 1;

    if ((id & 1) == 0) {
        // ================= idx half =================
        float* xs  = sm;                     // [128][XS_STRIDE]
        float* cst = sm + IDX_XS;            // [DSUB][KC]
        float* red = cst + IDX_CST;          // [3][128][17]
        float* c2p = red + IDX_RED;          // [16][8]
        float* c2s = c2p + IDX_C2P;          // [16]

        const int c   = w & 31;
        const int tb  = (w >> 5) * 128;
        const int tid = threadIdx.x;

        // stage x tile: 4096 float4 vecs, 16/thread in two 8-deep batches
#pragma unroll
        for (int b = 0; b < 2; b++) {
            float4 buf[8];
#pragma unroll
            for (int j = 0; j < 8; j++) {
                int i   = tid + (b * 8 + j) * 256;
                int row = i >> 5;
                int col = (i & 31) * 4;
                buf[j] = *(const float4*)&x[(size_t)(tb + row) * INF + c * DSUB + col];
            }
#pragma unroll
            for (int j = 0; j < 8; j++) {
                int i   = tid + (b * 8 + j) * 256;
                int row = i >> 5;
                int col = (i & 31) * 4;
                *(float4*)&xs[row * XS_STRIDE + col] = buf[j];
            }
        }
        for (int i = tid; i < KC * DSUB; i += 256) {
            int k = i >> 7, d = i & 127;
            cst[d * KC + k] = cent[(c * KC + k) * DSUB + d];
        }
        __syncthreads();

        if (tid < 128) {
            int k = tid >> 3, part = tid & 7;
            float s = 0.f;
            for (int d = part * 16; d < part * 16 + 16; d++) {
                float cv = cst[d * KC + k];
                s = fmaf(cv, cv, s);
            }
            c2p[k * 8 + part] = s;
        }
        __syncthreads();
        if (tid < 16) {
            float s = 0.f;
            for (int p = 0; p < 8; p++) s += c2p[tid * 8 + p];
            c2s[tid] = s;
        }
        __syncthreads();

        const int tp    = tid & 63;          // token pair base
        const int q     = tid >> 6;          // d-quarter 0..3
        const int t0    = tp;
        const int t1    = tp + 64;
        const int dbase = q * 32;

        float acc0[KC], acc1[KC];
#pragma unroll
        for (int k = 0; k < KC; k++) { acc0[k] = 0.f; acc1[k] = 0.f; }

        const float* xrA = &xs[t0 * XS_STRIDE];
        const float* xrB = &xs[t1 * XS_STRIDE];
        for (int d0 = dbase; d0 < dbase + 32; d0 += 4) {
            float4 xqA = *(const float4*)&xrA[d0];
            float4 xqB = *(const float4*)&xrB[d0];
            float xa[4] = {xqA.x, xqA.y, xqA.z, xqA.w};
            float xb[4] = {xqB.x, xqB.y, xqB.z, xqB.w};
#pragma unroll
            for (int j = 0; j < 4; j++) {
                const float4* cp = (const float4*)&cst[(d0 + j) * KC];
                float4 c0 = cp[0], c1 = cp[1], c2v = cp[2], c3 = cp[3];
                float xvA = xa[j], xvB = xb[j];
                ACC16(acc0, xvA);
                ACC16(acc1, xvB);
            }
        }

        if (q != 0) {
#pragma unroll
            for (int k = 0; k < KC; k++) {
                red[((q - 1) * 128 + t0) * 17 + k] = acc0[k];
                red[((q - 1) * 128 + t1) * 17 + k] = acc1[k];
            }
        }
        __syncthreads();
        if (q == 0) {
#pragma unroll
            for (int pass = 0; pass < 2; pass++) {
                const int token   = pass ? t1 : t0;
                const float* accp = pass ? acc1 : acc0;
                const float* xr   = pass ? xrB : xrA;
                float best = 1e30f, second = 1e30f;
                int bi = 0, si = 0;
#pragma unroll
                for (int k = 0; k < KC; k++) {
                    float dot = accp[k]
                              + red[(0 * 128 + token) * 17 + k]
                              + red[(1 * 128 + token) * 17 + k]
                              + red[(2 * 128 + token) * 17 + k];
                    float v = c2s[k] - 2.f * dot;
                    if (v < best)        { second = best; si = bi; best = v; bi = k; }
                    else if (v < second) { second = v; si = k; }
                }
                if (second - best < 1e-3f) {
                    double vb = 0.0, vs = 0.0;
                    for (int d = 0; d < DSUB; d++) {
                        double xv = (double)xr[d];
                        double cb = (double)cst[d * KC + bi];
                        double cs = (double)cst[d * KC + si];
                        vb += cb * (cb - 2.0 * xv);
                        vs += cs * (cs - 2.0 * xv);
                    }
                    if (vs < vb || (vs == vb && si < bi)) bi = si;
                }
                g_idx[(size_t)(tb + token) * NC + c] = (unsigned char)bi;
            }
        }
    } else {
        // ================= lut half =================
        float* cst = sm;                     // [DSUB][KC]
        float* red = sm + IDX_CST;           // [3][KC][128]

        const int c   = w & 31;
        const int tid = threadIdx.x;
        const int dq  = tid >> 6;            // d-quarter 0..3
        const int col = tid & 63;            // cols col and col+64

        for (int i = tid; i < KC * DSUB; i += 256) {
            int k = i >> 7, d = i & 127;
            cst[d * KC + k] = cent[(c * KC + k) * DSUB + d];
        }
        __syncthreads();

        const int ob = (w >> 5) * 128;
        const int oA = ob + col;
        const int oB = ob + col + 64;
        const float* wp = weight + (size_t)c * DSUB * OF + (size_t)(dq * 32) * OF;

        ull accA[8], accB[8];
#pragma unroll
        for (int p = 0; p < 8; p++) { accA[p] = 0ull; accB[p] = 0ull; }

#pragma unroll
        for (int half = 0; half < 2; half++) {
            float wA[16], wB[16];
#pragma unroll
            for (int i = 0; i < 16; i++) {
                wA[i] = wp[(size_t)(half * 16 + i) * OF + oA];
                wB[i] = wp[(size_t)(half * 16 + i) * OF + oB];
            }
#pragma unroll
            for (int i = 0; i < 16; i++) {
                ull wvA = pk2(wA[i], wA[i]);
                ull wvB = pk2(wB[i], wB[i]);
                const float* cp = &cst[(dq * 32 + half * 16 + i) * KC];
                ull a0, a1, a2, a3, a4, a5, a6, a7;
                lds_v2u64(a0, a1, cp);
                lds_v2u64(a2, a3, cp + 8);
                lds_v2u64(a4, a5, cp + 4);
                lds_v2u64(a6, a7, cp + 12);
                accA[0] = fma2(a0, wvA, accA[0]);
                accA[1] = fma2(a1, wvA, accA[1]);
                accA[2] = fma2(a2, wvA, accA[2]);
                accA[3] = fma2(a3, wvA, accA[3]);
                accA[4] = fma2(a4, wvA, accA[4]);
                accA[5] = fma2(a5, wvA, accA[5]);
                accA[6] = fma2(a6, wvA, accA[6]);
                accA[7] = fma2(a7, wvA, accA[7]);
                accB[0] = fma2(a0, wvB, accB[0]);
                accB[1] = fma2(a1, wvB, accB[1]);
                accB[2] = fma2(a2, wvB, accB[2]);
                accB[3] = fma2(a3, wvB, accB[3]);
                accB[4] = fma2(a4, wvB, accB[4]);
                accB[5] = fma2(a5, wvB, accB[5]);
                accB[6] = fma2(a6, wvB, accB[6]);
                accB[7] = fma2(a7, wvB, accB[7]);
            }
        }

        const int kmap[8] = {0, 1, 4, 5, 2, 3, 6, 7};

        if (dq != 0) {
#pragma unroll
            for (int p = 0; p < 8; p++) {
                float v0, v1, u0, u1;
                upk2(accA[p], v0, v1);
                upk2(accB[p], u0, u1);
                int kp = kmap[p];
                red[(((dq - 1) * KC) + kp * 2 + 0) * 128 + col]      = v0;
                red[(((dq - 1) * KC) + kp * 2 + 1) * 128 + col]      = v1;
                red[(((dq - 1) * KC) + kp * 2 + 0) * 128 + col + 64] = u0;
                red[(((dq - 1) * KC) + kp * 2 + 1) * 128 + col + 64] = u1;
            }
        }
        __syncthreads();
        if (dq == 0) {
#pragma unroll
            for (int p = 0; p < 8; p++) {
                float v0, v1, u0, u1;
                upk2(accA[p], v0, v1);
                upk2(accB[p], u0, u1);
                int k0 = kmap[p] * 2, k1 = k0 + 1;
                v0 = v0 + red[(0 * KC + k0) * 128 + col]
                        + red[(1 * KC + k0) * 128 + col]
                        + red[(2 * KC + k0) * 128 + col];
                v1 = v1 + red[(0 * KC + k1) * 128 + col]
                        + red[(1 * KC + k1) * 128 + col]
                        + red[(2 * KC + k1) * 128 + col];
                u0 = u0 + red[(0 * KC + k0) * 128 + col + 64]
                        + red[(1 * KC + k0) * 128 + col + 64]
                        + red[(2 * KC + k0) * 128 + col + 64];
                u1 = u1 + red[(0 * KC + k1) * 128 + col + 64]
                        + red[(1 * KC + k1) * 128 + col + 64]
                        + red[(2 * KC + k1) * 128 + col + 64];
                g_lut[(size_t)(c * KC + k0) * OF + oA] = v0;
                g_lut[(size_t)(c * KC + k1) * OF + oA] = v1;
                g_lut[(size_t)(c * KC + k0) * OF + oB] = u0;
                g_lut[(size_t)(c * KC + k1) * OF + oB] = u1;
            }
        }
    }
}

// ---------------------------------------------------------------------------
// K3: gather v3 — 512-token tiles (grid 256 = ONE wave at 2 CTAs/SM),
// 512 threads (32 warps/SM). Inner loop and accumulation order identical to
// v2 -> same bits.
// ---------------------------------------------------------------------------
__global__ __launch_bounds__(512, 2) void gather_kernel(float* __restrict__ out,
                                                        const float* __restrict__ bias)
{
    extern __shared__ float sm[];
    float*         lut_s = sm;                                  // [512][32] floats (64 KB)
    unsigned char* idx_s = (unsigned char*)(sm + NC * KC * 32); // 512*32 B (16 KB)

    const int ob  = blockIdx.x * 32;
    const int tb  = blockIdx.y * 512;
    const int tid = threadIdx.x;

    for (int i = tid; i < NC * KC * 32 / 4; i += 512) {
        int row = i >> 3;
        int col = (i & 7) * 4;
        float4 v = *(const float4*)&g_lut[(size_t)row * OF + ob + col];
        *(float4*)&lut_s[row * 32 + col] = v;
    }
    {
        const uint4* src = (const uint4*)&g_idx[(size_t)tb * NC];
        uint4* dst = (uint4*)idx_s;
        for (int i = tid; i < (512 * NC) / 16; i += 512) dst[i] = src[i];
    }
    __syncthreads();

    const int oq = tid & 7;    // o-quad
    const int tg = tid >> 3;   // token group 0..63
    const float4 bv = *(const float4*)&bias[ob + oq * 4];
    const float* lut_q = lut_s + oq * 4;

    for (int t = tg; t < 512; t += 64) {
        uint4 a = *(const uint4*)&idx_s[t * NC];
        uint4 b = *(const uint4*)&idx_s[t * NC + 16];
        unsigned int iw[8] = {a.x, a.y, a.z, a.w, b.x, b.y, b.z, b.w};
        float x0 = 0.f, y0 = 0.f, z0 = 0.f, w0 = 0.f;
        float x1 = 0.f, y1 = 0.f, z1 = 0.f, w1 = 0.f;
#pragma unroll
        for (int c = 0; c < NC; c++) {
            unsigned int k = (iw[c >> 2] >> ((c & 3) * 8)) & 0xFFu;
            float4 v = *(const float4*)&lut_q[c * 512 + k * 32];
            if (c & 1) { x1 += v.x; y1 += v.y; z1 += v.z; w1 += v.w; }
            else       { x0 += v.x; y0 += v.y; z0 += v.z; w0 += v.w; }
        }
        float4 r;
        r.x = (x0 + x1) + bv.x;
        r.y = (y0 + y1) + bv.y;
        r.z = (z0 + z1) + bv.z;
        r.w = (w0 + w1) + bv.w;
        *(float4*)&out[(size_t)(tb + t) * OF + ob + oq * 4] = r;
    }
}

// ---------------------------------------------------------------------------
extern "C" void kernel_launch(void* const* d_in, const int* in_sizes, int n_in,
                              void* d_out, int out_size)
{
    const float* x      = (const float*)d_in[0];
    const float* cent   = (const float*)d_in[1];
    const float* weight = (const float*)d_in[2];
    const float* bias   = (const float*)d_in[4];
    float* out = (float*)d_out;

    const int ntok = in_sizes[0] / INF;

    const int FUSED_SMEM = IDX_FLOATS * (int)sizeof(float);
    const int G_SMEM     = NC * KC * 32 * (int)sizeof(float) + 512 * NC;   // 80 KB

    cudaFuncSetAttribute(fused_idx_lut, cudaFuncAttributeMaxDynamicSharedMemorySize, FUSED_SMEM);
    cudaFuncSetAttribute(gather_kernel, cudaFuncAttributeMaxDynamicSharedMemorySize, G_SMEM);

    const int nblk = (ntok / 128) * NC;      // 512
    fused_idx_lut<<<nblk * 2, 256, FUSED_SMEM>>>(x, cent, weight);
    gather_kernel<<<dim3(OF / 32, ntok / 512), 512, G_SMEM>>>(out, bias);
}